// round 2
// baseline (speedup 1.0000x reference)
#include <cuda_runtime.h>
#include <cstdint>

typedef unsigned long long ull;

#define NW   4096
#define NHD  6
#define HD   32
#define CDIM 192
#define WS2  64
#define LDA  194
#define SMEM_BYTES ((64 * LDA + 192 * 64) * 4)   // 98816 B

// ---- scratch (device globals; runtime allocation forbidden) ----
__device__ float g_qkv[(size_t)3 * NW * NHD * WS2 * HD];   // [which][w][h][t][d]
__device__ float g_att[(size_t)NW * WS2 * CDIM];           // [w][t][h*32+d]
__device__ float g_qkvwT[192 * 576];                       // [c][o]
__device__ float g_projwT[192 * 192];                      // [c][o]

// ---- packed fp32x2 helpers ----
__device__ __forceinline__ ull dup2(float a) {
    ull r; asm("mov.b64 %0, {%1, %1};" : "=l"(r) : "f"(a)); return r;
}
__device__ __forceinline__ void fma2(ull& d, ull a, ull b) {
    asm("fma.rn.f32x2 %0, %1, %2, %0;" : "+l"(d) : "l"(a), "l"(b));
}
__device__ __forceinline__ ull add2(ull a, ull b) {
    ull r; asm("add.rn.f32x2 %0, %1, %2;" : "=l"(r) : "l"(a), "l"(b)); return r;
}
__device__ __forceinline__ ull mul2(ull a, ull b) {
    ull r; asm("mul.rn.f32x2 %0, %1, %2;" : "=l"(r) : "l"(a), "l"(b)); return r;
}
__device__ __forceinline__ float2 unpk(ull v) {
    float2 f; asm("mov.b64 {%0, %1}, %2;" : "=f"(f.x), "=f"(f.y) : "l"(v)); return f;
}

// ==================== prep: transpose weights ====================
__global__ void k_prep(const float* __restrict__ qkvw, const float* __restrict__ projw) {
    int o = blockIdx.x, c = threadIdx.x;
    if (o < 576) g_qkvwT[c * 576 + o] = qkvw[o * 192 + c];
    else         g_projwT[c * 192 + (o - 576)] = projw[(o - 576) * 192 + c];
}

// ==================== shared 64x64xK=192 GEMM core ====================
// As [64][LDA] m-major; Bs [192][64] k-major. 128 thr: ty=tid>>3, tx=tid&7.
__device__ __forceinline__ void gemm_core(const float* As, const float* Bs,
                                          int ty, int tx, ull acc[4][4]) {
    const float* ap = As + (ty << 2) * LDA;
#pragma unroll 8
    for (int k = 0; k < 192; ++k) {
        const ull* bp = (const ull*)(Bs + (k << 6) + (tx << 3));
        ull b0 = bp[0], b1 = bp[1], b2 = bp[2], b3 = bp[3];
#pragma unroll
        for (int i = 0; i < 4; ++i) {
            ull aa = dup2(ap[i * LDA + k]);
            fma2(acc[i][0], aa, b0);
            fma2(acc[i][1], aa, b1);
            fma2(acc[i][2], aa, b2);
            fma2(acc[i][3], aa, b3);
        }
    }
}

// ==================== K1: QKV GEMM ====================
// grid(9, 4096): x = N-tile, y = window.
__global__ __launch_bounds__(128) void k_qkv(const float* __restrict__ x) {
    extern __shared__ float sm[];
    float* As = sm;
    float* Bs = sm + 64 * LDA;
    int nt = blockIdx.x, w = blockIdx.y, tid = threadIdx.x;
    int b = w >> 10, wh = (w >> 5) & 31, ww = w & 31;
    const float* xw = x + (size_t)(((b << 8) + (wh << 3)) * 256 + (ww << 3)) * CDIM;

#pragma unroll
    for (int it = 0; it < 24; ++it) {
        int idx = it * 128 + tid;
        int r = idx / 48, c4 = idx - r * 48;
        float4 v = *(const float4*)(xw + (size_t)(((r >> 3) << 8) + (r & 7)) * CDIM + (c4 << 2));
        float2* d2 = (float2*)(As + r * LDA + (c4 << 2));
        d2[0] = make_float2(v.x, v.y);
        d2[1] = make_float2(v.z, v.w);
    }
    const float* wsrc = g_qkvwT + nt * 64;
#pragma unroll
    for (int it = 0; it < 24; ++it) {
        int idx = it * 128 + tid;
        int c = idx >> 4, o4 = idx & 15;
        *(float4*)(Bs + (c << 6) + (o4 << 2)) = *(const float4*)(wsrc + c * 576 + (o4 << 2));
    }
    __syncthreads();

    int ty = tid >> 3, tx = tid & 7;
    ull acc[4][4];
#pragma unroll
    for (int i = 0; i < 4; ++i)
#pragma unroll
        for (int j = 0; j < 4; ++j) acc[i][j] = 0ull;

    gemm_core(As, Bs, ty, tx, acc);

    int o0 = nt * 64 + (tx << 3);
    int which = o0 / 192;
    int rem = o0 - which * 192;
    int h = rem >> 5, d0 = rem & 31;
    ull sc = dup2(which == 0 ? 0.17677669529663687f : 1.0f);
    float* dst0 = g_qkv + (((size_t)(which * NW + w) * NHD + h) * WS2 + (ty << 2)) * HD + d0;
#pragma unroll
    for (int i = 0; i < 4; ++i) {
        ulonglong2* p = (ulonglong2*)(dst0 + (size_t)i * HD);
        p[0] = make_ulonglong2(mul2(acc[i][0], sc), mul2(acc[i][1], sc));
        p[1] = make_ulonglong2(mul2(acc[i][2], sc), mul2(acc[i][3], sc));
    }
}

// ==================== K2: windowed attention ====================
// grid(6, 4096): x = head, y = window. 64 thr; thread = one query row.
__global__ __launch_bounds__(64) void k_attn(const float* __restrict__ rpb) {
    __shared__ float ks[2048], vs[2048], bias_s[240];
    int h = blockIdx.x, w = blockIdx.y, tid = threadIdx.x;
    size_t base = ((size_t)(w * NHD + h)) << 11;
    const size_t plane = (size_t)NW * NHD * 2048;
    const float4* kp4 = (const float4*)(g_qkv + plane + base);
    const float4* vp4 = (const float4*)(g_qkv + 2 * plane + base);
#pragma unroll
    for (int u = 0; u < 8; ++u) {
        ((float4*)ks)[(u << 6) + tid] = kp4[(u << 6) + tid];
        ((float4*)vs)[(u << 6) + tid] = vp4[(u << 6) + tid];
    }
    for (int i = tid; i < 225; i += 64) bias_s[i] = rpb[i * NHD + h];
    __syncthreads();

    ull qr[16];
    const ull* qp = (const ull*)(g_qkv + base + (size_t)tid * HD);
#pragma unroll
    for (int i = 0; i < 16; ++i) qr[i] = qp[i];

    int qi = tid >> 3, qj = tid & 7;
    ull acc[16];
#pragma unroll
    for (int i = 0; i < 16; ++i) acc[i] = 0ull;
    float sum = 0.0f;

#pragma unroll 8
    for (int kk = 0; kk < 64; ++kk) {
        const ull* kr = (const ull*)(ks + (kk << 5));
        ull e0 = 0ull, e1 = 0ull;
#pragma unroll
        for (int i = 0; i < 8; ++i) {
            fma2(e0, qr[2 * i], kr[2 * i]);
            fma2(e1, qr[2 * i + 1], kr[2 * i + 1]);
        }
        float2 f = unpk(add2(e0, e1));
        int ki = kk >> 3, kj = kk & 7;
        float sv = f.x + f.y + bias_s[(qi - ki + 7) * 15 + (qj - kj + 7)];
        float p = __expf(sv);
        sum += p;
        ull pv = dup2(p);
        const ull* vr = (const ull*)(vs + (kk << 5));
#pragma unroll
        for (int i = 0; i < 16; ++i) fma2(acc[i], pv, vr[i]);
    }

    ull inv = dup2(1.0f / sum);
    // out -> g_att[w][t][h*32+d]
    ull* op = (ull*)(g_att + ((size_t)w * WS2 + tid) * CDIM + h * HD);
#pragma unroll
    for (int i = 0; i < 16; ++i) op[i] = mul2(acc[i], inv);
}

// ==================== K3: projection + bias + scatter ====================
// grid(3, 4096): x = N-tile, y = window.
__global__ __launch_bounds__(128) void k_proj(const float* __restrict__ pb,
                                              float* __restrict__ out) {
    extern __shared__ float sm[];
    float* As = sm;
    float* Bs = sm + 64 * LDA;
    int nt = blockIdx.x, w = blockIdx.y, tid = threadIdx.x;

    const float* asrc = g_att + (size_t)w * (WS2 * CDIM);
#pragma unroll
    for (int it = 0; it < 24; ++it) {
        int idx = it * 128 + tid;
        int r = idx / 48, c4 = idx - r * 48;
        float4 v = *(const float4*)(asrc + (size_t)idx * 4);
        float2* d2 = (float2*)(As + r * LDA + (c4 << 2));
        d2[0] = make_float2(v.x, v.y);
        d2[1] = make_float2(v.z, v.w);
    }
    const float* wsrc = g_projwT + nt * 64;
#pragma unroll
    for (int it = 0; it < 24; ++it) {
        int idx = it * 128 + tid;
        int c = idx >> 4, o4 = idx & 15;
        *(float4*)(Bs + (c << 6) + (o4 << 2)) = *(const float4*)(wsrc + c * 192 + (o4 << 2));
    }
    __syncthreads();

    int ty = tid >> 3, tx = tid & 7;
    ull acc[4][4];
#pragma unroll
    for (int i = 0; i < 4; ++i)
#pragma unroll
        for (int j = 0; j < 4; ++j) acc[i][j] = 0ull;

    gemm_core(As, Bs, ty, tx, acc);

    int o0 = nt * 64 + (tx << 3);
    const ull* bb = (const ull*)(pb + o0);
    ull b0 = bb[0], b1 = bb[1], b2 = bb[2], b3 = bb[3];

    int b = w >> 10, wh = (w >> 5) & 31, ww = w & 31;
#pragma unroll
    for (int i = 0; i < 4; ++i) {
        int t = (ty << 2) + i;
        int ri = t >> 3, ci = t & 7;
        size_t pix = (size_t)((b << 8) + (wh << 3) + ri) * 256 + (ww << 3) + ci;
        ulonglong2* p = (ulonglong2*)(out + pix * CDIM + o0);
        p[0] = make_ulonglong2(add2(acc[i][0], b0), add2(acc[i][1], b1));
        p[1] = make_ulonglong2(add2(acc[i][2], b2), add2(acc[i][3], b3));
    }
}

// ==================== launch ====================
extern "C" void kernel_launch(void* const* d_in, const int* in_sizes, int n_in,
                              void* d_out, int out_size) {
    const float* x     = (const float*)d_in[0];
    const float* qkvw  = (const float*)d_in[1];
    const float* projw = (const float*)d_in[2];
    const float* pb    = (const float*)d_in[3];
    const float* rpb   = (const float*)d_in[4];
    (void)in_sizes; (void)n_in; (void)out_size;

    cudaFuncSetAttribute(k_qkv,  cudaFuncAttributeMaxDynamicSharedMemorySize, SMEM_BYTES);
    cudaFuncSetAttribute(k_proj, cudaFuncAttributeMaxDynamicSharedMemorySize, SMEM_BYTES);

    k_prep<<<768, 192>>>(qkvw, projw);
    k_qkv <<<dim3(9, NW), 128, SMEM_BYTES>>>(x);
    k_attn<<<dim3(NHD, NW), 64>>>(rpb);
    k_proj<<<dim3(3, NW), 128, SMEM_BYTES>>>(pb, (float*)d_out);
}

// round 3
// speedup vs baseline: 1.0818x; 1.0818x over previous
#include <cuda_runtime.h>
#include <cstdint>

typedef unsigned long long ull;

#define NW   4096
#define NHD  6
#define HD   32
#define CDIM 192
#define WS2  64
#define LDA  194
#define SMEM_BYTES ((64 * LDA + 192 * 64) * 4)   // 98816 B

// ---- scratch (device globals; runtime allocation forbidden) ----
__device__ float g_qkv[(size_t)3 * NW * NHD * WS2 * HD];   // [which][w][h][t][d]
__device__ float g_att[(size_t)NW * WS2 * CDIM];           // [w][t][h*32+d]
__device__ float g_qkvwT[192 * 576];                       // [c][o]
__device__ float g_projwT[192 * 192];                      // [c][o]

// ---- packed fp32x2 helpers ----
__device__ __forceinline__ ull dup2(float a) {
    ull r; asm("mov.b64 %0, {%1, %1};" : "=l"(r) : "f"(a)); return r;
}
__device__ __forceinline__ void fma2(ull& d, ull a, ull b) {
    asm("fma.rn.f32x2 %0, %1, %2, %0;" : "+l"(d) : "l"(a), "l"(b));
}
__device__ __forceinline__ ull add2(ull a, ull b) {
    ull r; asm("add.rn.f32x2 %0, %1, %2;" : "=l"(r) : "l"(a), "l"(b)); return r;
}
__device__ __forceinline__ ull mul2(ull a, ull b) {
    ull r; asm("mul.rn.f32x2 %0, %1, %2;" : "=l"(r) : "l"(a), "l"(b)); return r;
}
__device__ __forceinline__ float2 unpk(ull v) {
    float2 f; asm("mov.b64 {%0, %1}, %2;" : "=f"(f.x), "=f"(f.y) : "l"(v)); return f;
}

// ==================== prep: transpose weights ====================
__global__ void k_prep(const float* __restrict__ qkvw, const float* __restrict__ projw) {
    int o = blockIdx.x, c = threadIdx.x;
    if (o < 576) g_qkvwT[c * 576 + o] = qkvw[o * 192 + c];
    else         g_projwT[c * 192 + (o - 576)] = projw[(o - 576) * 192 + c];
}

// ==================== 64x64xK=192 GEMM core, 64 thr, 8x8/thread ==========
// As [64][LDA] m-major; Bs [192][64] k-major. ty=tid>>3 (0..7), tx=tid&7.
__device__ __forceinline__ void gemm_core(const float* As, const float* Bs,
                                          int ty, int tx, ull acc[8][4]) {
    const float* ap = As + (ty << 3) * LDA;
#pragma unroll 4
    for (int k = 0; k < 192; ++k) {
        const ulonglong2* bp = (const ulonglong2*)(Bs + (k << 6) + (tx << 3));
        ulonglong2 bA = bp[0], bB = bp[1];
#pragma unroll
        for (int i = 0; i < 8; ++i) {
            ull aa = dup2(ap[i * LDA + k]);
            fma2(acc[i][0], aa, bA.x);
            fma2(acc[i][1], aa, bA.y);
            fma2(acc[i][2], aa, bB.x);
            fma2(acc[i][3], aa, bB.y);
        }
    }
}

// ==================== K1: QKV GEMM ====================
// grid(9, 4096): x = N-tile, y = window. 64 threads.
__global__ __launch_bounds__(64) void k_qkv(const float* __restrict__ x) {
    extern __shared__ float sm[];
    float* As = sm;
    float* Bs = sm + 64 * LDA;
    int nt = blockIdx.x, w = blockIdx.y, tid = threadIdx.x;
    int b = w >> 10, wh = (w >> 5) & 31, ww = w & 31;
    const float* xw = x + (size_t)(((b << 8) + (wh << 3)) * 256 + (ww << 3)) * CDIM;

#pragma unroll
    for (int it = 0; it < 48; ++it) {
        int idx = it * 64 + tid;
        int r = idx / 48, c4 = idx - r * 48;
        float4 v = *(const float4*)(xw + (size_t)(((r >> 3) << 8) + (r & 7)) * CDIM + (c4 << 2));
        float2* d2 = (float2*)(As + r * LDA + (c4 << 2));
        d2[0] = make_float2(v.x, v.y);
        d2[1] = make_float2(v.z, v.w);
    }
    const float* wsrc = g_qkvwT + nt * 64;
#pragma unroll
    for (int it = 0; it < 48; ++it) {
        int idx = it * 64 + tid;
        int c = idx >> 4, o4 = idx & 15;
        *(float4*)(Bs + (c << 6) + (o4 << 2)) = *(const float4*)(wsrc + c * 576 + (o4 << 2));
    }
    __syncthreads();

    int ty = tid >> 3, tx = tid & 7;
    ull acc[8][4];
#pragma unroll
    for (int i = 0; i < 8; ++i)
#pragma unroll
        for (int j = 0; j < 4; ++j) acc[i][j] = 0ull;

    gemm_core(As, Bs, ty, tx, acc);

    int o0 = nt * 64 + (tx << 3);
    int which = o0 / 192;
    int rem = o0 - which * 192;
    int h = rem >> 5, d0 = rem & 31;
    ull sc = dup2(which == 0 ? 0.17677669529663687f : 1.0f);
    float* dst0 = g_qkv + (((size_t)(which * NW + w) * NHD + h) * WS2 + (ty << 3)) * HD + d0;
#pragma unroll
    for (int i = 0; i < 8; ++i) {
        ulonglong2* p = (ulonglong2*)(dst0 + (size_t)i * HD);
        p[0] = make_ulonglong2(mul2(acc[i][0], sc), mul2(acc[i][1], sc));
        p[1] = make_ulonglong2(mul2(acc[i][2], sc), mul2(acc[i][3], sc));
    }
}

// ==================== K2: windowed attention ====================
// grid(6, 4096): x = head, y = window. 32 threads; thread = 2 query rows.
__global__ __launch_bounds__(32) void k_attn(const float* __restrict__ rpb) {
    __shared__ float ks[2048], vs[2048], bias_s[240];
    int h = blockIdx.x, w = blockIdx.y, lane = threadIdx.x;
    size_t base = ((size_t)(w * NHD + h)) << 11;
    const size_t plane = (size_t)NW * NHD * 2048;
    const float4* kp4 = (const float4*)(g_qkv + plane + base);
    const float4* vp4 = (const float4*)(g_qkv + 2 * plane + base);
#pragma unroll
    for (int u = 0; u < 16; ++u) {
        ((float4*)ks)[(u << 5) + lane] = kp4[(u << 5) + lane];
        ((float4*)vs)[(u << 5) + lane] = vp4[(u << 5) + lane];
    }
    for (int i = lane; i < 225; i += 32) bias_s[i] = rpb[i * NHD + h];
    __syncthreads();

    int q0 = lane << 1, q1 = q0 + 1;
    ull qr0[16], qr1[16];
    const ull* qp = (const ull*)(g_qkv + base + (size_t)q0 * HD);
#pragma unroll
    for (int i = 0; i < 16; ++i) { qr0[i] = qp[i]; qr1[i] = qp[16 + i]; }

    int q0i = q0 >> 3, q0j = q0 & 7;
    int q1i = q1 >> 3, q1j = q1 & 7;
    ull acc0[16], acc1[16];
#pragma unroll
    for (int i = 0; i < 16; ++i) { acc0[i] = 0ull; acc1[i] = 0ull; }
    float sum0 = 0.0f, sum1 = 0.0f;

#pragma unroll 4
    for (int kk = 0; kk < 64; ++kk) {
        const ull* kr = (const ull*)(ks + (kk << 5));
        ull e00 = 0ull, e01 = 0ull, e10 = 0ull, e11 = 0ull;
#pragma unroll
        for (int i = 0; i < 8; ++i) {
            ull k0 = kr[2 * i], k1 = kr[2 * i + 1];
            fma2(e00, qr0[2 * i], k0);
            fma2(e01, qr0[2 * i + 1], k1);
            fma2(e10, qr1[2 * i], k0);
            fma2(e11, qr1[2 * i + 1], k1);
        }
        int ki = kk >> 3, kj = kk & 7;
        int bidx = (7 - ki) * 15 + (7 - kj);
        float2 f0 = unpk(add2(e00, e01));
        float2 f1 = unpk(add2(e10, e11));
        float s0 = f0.x + f0.y + bias_s[bidx + q0i * 15 + q0j];
        float s1 = f1.x + f1.y + bias_s[bidx + q1i * 15 + q1j];
        float p0 = __expf(s0);
        float p1 = __expf(s1);
        sum0 += p0; sum1 += p1;
        ull pv0 = dup2(p0), pv1 = dup2(p1);
        const ull* vr = (const ull*)(vs + (kk << 5));
#pragma unroll
        for (int i = 0; i < 16; ++i) {
            ull vv = vr[i];
            fma2(acc0[i], pv0, vv);
            fma2(acc1[i], pv1, vv);
        }
    }

    ull inv0 = dup2(1.0f / sum0);
    ull inv1 = dup2(1.0f / sum1);
    ull* op0 = (ull*)(g_att + ((size_t)w * WS2 + q0) * CDIM + h * HD);
    ull* op1 = (ull*)(g_att + ((size_t)w * WS2 + q1) * CDIM + h * HD);
#pragma unroll
    for (int i = 0; i < 16; ++i) {
        op0[i] = mul2(acc0[i], inv0);
        op1[i] = mul2(acc1[i], inv1);
    }
}

// ==================== K3: projection + bias + scatter ====================
// grid(3, 4096): x = N-tile, y = window. 64 threads.
__global__ __launch_bounds__(64) void k_proj(const float* __restrict__ pb,
                                             float* __restrict__ out) {
    extern __shared__ float sm[];
    float* As = sm;
    float* Bs = sm + 64 * LDA;
    int nt = blockIdx.x, w = blockIdx.y, tid = threadIdx.x;

    const float* asrc = g_att + (size_t)w * (WS2 * CDIM);
#pragma unroll
    for (int it = 0; it < 48; ++it) {
        int idx = it * 64 + tid;
        int r = idx / 48, c4 = idx - r * 48;
        float4 v = *(const float4*)(asrc + (size_t)idx * 4);
        float2* d2 = (float2*)(As + r * LDA + (c4 << 2));
        d2[0] = make_float2(v.x, v.y);
        d2[1] = make_float2(v.z, v.w);
    }
    const float* wsrc = g_projwT + nt * 64;
#pragma unroll
    for (int it = 0; it < 48; ++it) {
        int idx = it * 64 + tid;
        int c = idx >> 4, o4 = idx & 15;
        *(float4*)(Bs + (c << 6) + (o4 << 2)) = *(const float4*)(wsrc + c * 192 + (o4 << 2));
    }
    __syncthreads();

    int ty = tid >> 3, tx = tid & 7;
    ull acc[8][4];
#pragma unroll
    for (int i = 0; i < 8; ++i)
#pragma unroll
        for (int j = 0; j < 4; ++j) acc[i][j] = 0ull;

    gemm_core(As, Bs, ty, tx, acc);

    int o0 = nt * 64 + (tx << 3);
    const ull* bb = (const ull*)(pb + o0);
    ull b0 = bb[0], b1 = bb[1], b2 = bb[2], b3 = bb[3];

    int b = w >> 10, wh = (w >> 5) & 31, ww = w & 31;
#pragma unroll
    for (int i = 0; i < 8; ++i) {
        int t = (ty << 3) + i;
        int ri = t >> 3, ci = t & 7;
        size_t pix = (size_t)((b << 8) + (wh << 3) + ri) * 256 + (ww << 3) + ci;
        ulonglong2* p = (ulonglong2*)(out + pix * CDIM + o0);
        p[0] = make_ulonglong2(add2(acc[i][0], b0), add2(acc[i][1], b1));
        p[1] = make_ulonglong2(add2(acc[i][2], b2), add2(acc[i][3], b3));
    }
}

// ==================== launch ====================
extern "C" void kernel_launch(void* const* d_in, const int* in_sizes, int n_in,
                              void* d_out, int out_size) {
    const float* x     = (const float*)d_in[0];
    const float* qkvw  = (const float*)d_in[1];
    const float* projw = (const float*)d_in[2];
    const float* pb    = (const float*)d_in[3];
    const float* rpb   = (const float*)d_in[4];
    (void)in_sizes; (void)n_in; (void)out_size;

    cudaFuncSetAttribute(k_qkv,  cudaFuncAttributeMaxDynamicSharedMemorySize, SMEM_BYTES);
    cudaFuncSetAttribute(k_proj, cudaFuncAttributeMaxDynamicSharedMemorySize, SMEM_BYTES);

    k_prep<<<768, 192>>>(qkvw, projw);
    k_qkv <<<dim3(9, NW), 64, SMEM_BYTES>>>(x);
    k_attn<<<dim3(NHD, NW), 32>>>(rpb);
    k_proj<<<dim3(3, NW), 64, SMEM_BYTES>>>(pb, (float*)d_out);
}

// round 6
// speedup vs baseline: 1.2911x; 1.1935x over previous
#include <cuda_runtime.h>
#include <cstdint>

typedef unsigned long long ull;

#define NW   4096
#define NHD  6
#define HD   32
#define CDIM 192
#define WS2  64

// Skewed k-major-pair layouts (conflict-free compute loads):
// As row m at OFFA(m) = m*194 + (m>>3)*20   (a-load groups hit distinct banks)
// Bs row n at OFFB(n) = n*194 + (n>>2)*26   (16 b-lanes cover all 32 banks)
#define OFFA(m) ((m) * 194 + ((m) >> 3) * 20)
#define OFFB(n) ((n) * 194 + ((n) >> 2) * 26)
#define AS_FLOATS 12560
#define BS_FLOATS 12816
#define SMEM_BYTES ((AS_FLOATS + BS_FLOATS) * 4)   // 101504 B -> 2 CTA/SM

// ---- scratch (device globals; runtime allocation forbidden) ----
__device__ float g_qkv[(size_t)3 * NW * NHD * WS2 * HD];   // [which][w][h][t][d]
__device__ float g_att[(size_t)NW * WS2 * CDIM];           // [w][t][h*32+d]

// ---- packed fp32x2 helpers ----
__device__ __forceinline__ ull dup2(float a) {
    ull r; asm("mov.b64 %0, {%1, %1};" : "=l"(r) : "f"(a)); return r;
}
__device__ __forceinline__ void fma2(ull& d, ull a, ull b) {
    asm("fma.rn.f32x2 %0, %1, %2, %0;" : "+l"(d) : "l"(a), "l"(b));
}
__device__ __forceinline__ ull add2(ull a, ull b) {
    ull r; asm("add.rn.f32x2 %0, %1, %2;" : "=l"(r) : "l"(a), "l"(b)); return r;
}
__device__ __forceinline__ ull mul2(ull a, ull b) {
    ull r; asm("mul.rn.f32x2 %0, %1, %2;" : "=l"(r) : "l"(a), "l"(b)); return r;
}
__device__ __forceinline__ float2 unpk(ull v) {
    float2 f; asm("mov.b64 {%0, %1}, %2;" : "=f"(f.x), "=f"(f.y) : "l"(v)); return f;
}
__device__ __forceinline__ float hsum(ull v) {
    float2 f = unpk(v); return f.x + f.y;
}

// ==================== GEMM core: 64x64, K=192, k-pair packed ====================
// 128 thr: ty=tid>>4 (0..7) -> m0=ty*8;  tx=tid&15 (0..15) -> n0=tx*4.
// acc[i][j] halves hold even-k / odd-k partial sums; final = hsum.
__device__ __forceinline__ void gemm_core(const float* As, const float* Bs,
                                          int ty, int tx, ull acc[8][4]) {
    const float* ap = As + ty * 1572;   // 8*194 + 20
    const float* bp = Bs + tx * 802;    // 4*194 + 26
    ull a0[8], b0[4], a1[8], b1[4];
#pragma unroll
    for (int i = 0; i < 8; ++i) a0[i] = *(const ull*)(ap + i * 194);
#pragma unroll
    for (int j = 0; j < 4; ++j) b0[j] = *(const ull*)(bp + j * 194);
#pragma unroll 1
    for (int k2 = 0; k2 < 96; k2 += 2) {
#pragma unroll
        for (int i = 0; i < 8; ++i) a1[i] = *(const ull*)(ap + i * 194 + 2 * (k2 + 1));
#pragma unroll
        for (int j = 0; j < 4; ++j) b1[j] = *(const ull*)(bp + j * 194 + 2 * (k2 + 1));
#pragma unroll
        for (int i = 0; i < 8; ++i)
#pragma unroll
            for (int j = 0; j < 4; ++j) fma2(acc[i][j], a0[i], b0[j]);
        // prefetch k2+2 (last iter reads in-bounds padding, never used)
#pragma unroll
        for (int i = 0; i < 8; ++i) a0[i] = *(const ull*)(ap + i * 194 + 2 * (k2 + 2));
#pragma unroll
        for (int j = 0; j < 4; ++j) b0[j] = *(const ull*)(bp + j * 194 + 2 * (k2 + 2));
#pragma unroll
        for (int i = 0; i < 8; ++i)
#pragma unroll
            for (int j = 0; j < 4; ++j) fma2(acc[i][j], a1[i], b1[j]);
    }
}

// ==================== K1: QKV GEMM ====================
// grid(9, 4096): x = N-tile (576/64), y = window. 128 threads.
__global__ __launch_bounds__(128) void k_qkv(const float* __restrict__ x,
                                             const float* __restrict__ qkvw) {
    extern __shared__ float sm[];
    float* As = sm;
    float* Bs = sm + AS_FLOATS;
    int nt = blockIdx.x, w = blockIdx.y, tid = threadIdx.x;
    int b = w >> 10, wh = (w >> 5) & 31, ww = w & 31;
    const float* xw = x + (size_t)(((b << 8) + (wh << 3)) * 256 + (ww << 3)) * CDIM;

    // As: 64 window rows x 192 ch (m-major, skewed rows)
#pragma unroll
    for (int it = 0; it < 24; ++it) {
        int idx = it * 128 + tid;
        int r = idx / 48, c4 = idx - r * 48;
        float4 v = *(const float4*)(xw + (size_t)(((r >> 3) << 8) + (r & 7)) * CDIM + (c4 << 2));
        float* d = As + OFFA(r) + (c4 << 2);
        *(float2*)(d)     = make_float2(v.x, v.y);
        *(float2*)(d + 2) = make_float2(v.z, v.w);
    }
    // Bs: weight rows nt*64..+63 read directly (already n-major k-contiguous)
#pragma unroll
    for (int it = 0; it < 24; ++it) {
        int idx = it * 128 + tid;
        int n = idx / 48, c4 = idx - n * 48;
        float4 v = *(const float4*)(qkvw + (size_t)(nt * 64 + n) * CDIM + (c4 << 2));
        float* d = Bs + OFFB(n) + (c4 << 2);
        *(float2*)(d)     = make_float2(v.x, v.y);
        *(float2*)(d + 2) = make_float2(v.z, v.w);
    }
    __syncthreads();

    int ty = tid >> 4, tx = tid & 15;
    ull acc[8][4];
#pragma unroll
    for (int i = 0; i < 8; ++i)
#pragma unroll
        for (int j = 0; j < 4; ++j) acc[i][j] = 0ull;

    gemm_core(As, Bs, ty, tx, acc);

    int o0 = nt * 64 + (tx << 2);
    int which = o0 / 192;
    int rem = o0 - which * 192;
    int h = rem >> 5, d0 = rem & 31;
    float scale = (which == 0) ? 0.17677669529663687f : 1.0f;
    int m0 = ty << 3;
    float* dst = g_qkv + (((size_t)(which * NW + w) * NHD + h) * WS2 + m0) * HD + d0;
#pragma unroll
    for (int i = 0; i < 8; ++i) {
        float4 v = make_float4(hsum(acc[i][0]) * scale, hsum(acc[i][1]) * scale,
                               hsum(acc[i][2]) * scale, hsum(acc[i][3]) * scale);
        *(float4*)(dst + (size_t)i * HD) = v;
    }
}

// ==================== K2: windowed attention (unchanged from R3) ====================
// grid(6, 4096): x = head, y = window. 32 thr; thread = 2 query rows.
__global__ __launch_bounds__(32) void k_attn(const float* __restrict__ rpb) {
    __shared__ float ks[2048], vs[2048], bias_s[240];
    int h = blockIdx.x, w = blockIdx.y, lane = threadIdx.x;
    size_t base = ((size_t)(w * NHD + h)) << 11;
    const size_t plane = (size_t)NW * NHD * 2048;
    const float4* kp4 = (const float4*)(g_qkv + plane + base);
    const float4* vp4 = (const float4*)(g_qkv + 2 * plane + base);
#pragma unroll
    for (int u = 0; u < 16; ++u) {
        ((float4*)ks)[(u << 5) + lane] = kp4[(u << 5) + lane];
        ((float4*)vs)[(u << 5) + lane] = vp4[(u << 5) + lane];
    }
    for (int i = lane; i < 225; i += 32) bias_s[i] = rpb[i * NHD + h];
    __syncthreads();

    int q0 = lane << 1, q1 = q0 + 1;
    ull qr0[16], qr1[16];
    const ull* qp = (const ull*)(g_qkv + base + (size_t)q0 * HD);
#pragma unroll
    for (int i = 0; i < 16; ++i) { qr0[i] = qp[i]; qr1[i] = qp[16 + i]; }

    int q0i = q0 >> 3, q0j = q0 & 7;
    int q1i = q1 >> 3, q1j = q1 & 7;
    ull acc0[16], acc1[16];
#pragma unroll
    for (int i = 0; i < 16; ++i) { acc0[i] = 0ull; acc1[i] = 0ull; }
    float sum0 = 0.0f, sum1 = 0.0f;

#pragma unroll 4
    for (int kk = 0; kk < 64; ++kk) {
        const ull* kr = (const ull*)(ks + (kk << 5));
        ull e00 = 0ull, e01 = 0ull, e10 = 0ull, e11 = 0ull;
#pragma unroll
        for (int i = 0; i < 8; ++i) {
            ull k0 = kr[2 * i], k1 = kr[2 * i + 1];
            fma2(e00, qr0[2 * i], k0);
            fma2(e01, qr0[2 * i + 1], k1);
            fma2(e10, qr1[2 * i], k0);
            fma2(e11, qr1[2 * i + 1], k1);
        }
        int ki = kk >> 3, kj = kk & 7;
        int bidx = (7 - ki) * 15 + (7 - kj);
        float2 f0 = unpk(add2(e00, e01));
        float2 f1 = unpk(add2(e10, e11));
        float p0 = __expf(f0.x + f0.y + bias_s[bidx + q0i * 15 + q0j]);
        float p1 = __expf(f1.x + f1.y + bias_s[bidx + q1i * 15 + q1j]);
        sum0 += p0; sum1 += p1;
        ull pv0 = dup2(p0), pv1 = dup2(p1);
        const ull* vr = (const ull*)(vs + (kk << 5));
#pragma unroll
        for (int i = 0; i < 16; ++i) {
            ull vv = vr[i];
            fma2(acc0[i], pv0, vv);
            fma2(acc1[i], pv1, vv);
        }
    }

    ull inv0 = dup2(1.0f / sum0), inv1 = dup2(1.0f / sum1);
    ull* op0 = (ull*)(g_att + ((size_t)w * WS2 + q0) * CDIM + h * HD);
    ull* op1 = (ull*)(g_att + ((size_t)w * WS2 + q1) * CDIM + h * HD);
#pragma unroll
    for (int i = 0; i < 16; ++i) {
        op0[i] = mul2(acc0[i], inv0);
        op1[i] = mul2(acc1[i], inv1);
    }
}

// ==================== K3: projection + bias + scatter ====================
// grid(3, 4096): x = N-tile, y = window. 128 threads.
__global__ __launch_bounds__(128) void k_proj(const float* __restrict__ projw,
                                              const float* __restrict__ pb,
                                              float* __restrict__ out) {
    extern __shared__ float sm[];
    float* As = sm;
    float* Bs = sm + AS_FLOATS;
    int nt = blockIdx.x, w = blockIdx.y, tid = threadIdx.x;

    const float* asrc = g_att + (size_t)w * (WS2 * CDIM);
#pragma unroll
    for (int it = 0; it < 24; ++it) {
        int idx = it * 128 + tid;
        int r = idx / 48, c4 = idx - r * 48;
        float4 v = *(const float4*)(asrc + (size_t)idx * 4);
        float* d = As + OFFA(r) + (c4 << 2);
        *(float2*)(d)     = make_float2(v.x, v.y);
        *(float2*)(d + 2) = make_float2(v.z, v.w);
    }
#pragma unroll
    for (int it = 0; it < 24; ++it) {
        int idx = it * 128 + tid;
        int n = idx / 48, c4 = idx - n * 48;
        float4 v = *(const float4*)(projw + (size_t)(nt * 64 + n) * CDIM + (c4 << 2));
        float* d = Bs + OFFB(n) + (c4 << 2);
        *(float2*)(d)     = make_float2(v.x, v.y);
        *(float2*)(d + 2) = make_float2(v.z, v.w);
    }
    __syncthreads();

    int ty = tid >> 4, tx = tid & 15;
    ull acc[8][4];
#pragma unroll
    for (int i = 0; i < 8; ++i)
#pragma unroll
        for (int j = 0; j < 4; ++j) acc[i][j] = 0ull;

    gemm_core(As, Bs, ty, tx, acc);

    int o0 = nt * 64 + (tx << 2);
    float4 bias = *(const float4*)(pb + o0);
    int m0 = ty << 3;
    int b = w >> 10, wh = (w >> 5) & 31, ww = w & 31;
#pragma unroll
    for (int i = 0; i < 8; ++i) {
        int t = m0 + i;
        int ri = t >> 3, ci = t & 7;
        size_t pix = (size_t)((b << 8) + (wh << 3) + ri) * 256 + (ww << 3) + ci;
        float4 v = make_float4(hsum(acc[i][0]) + bias.x, hsum(acc[i][1]) + bias.y,
                               hsum(acc[i][2]) + bias.z, hsum(acc[i][3]) + bias.w);
        *(float4*)(out + pix * CDIM + o0) = v;
    }
}

// ==================== launch ====================
extern "C" void kernel_launch(void* const* d_in, const int* in_sizes, int n_in,
                              void* d_out, int out_size) {
    const float* x     = (const float*)d_in[0];
    const float* qkvw  = (const float*)d_in[1];
    const float* projw = (const float*)d_in[2];
    const float* pb    = (const float*)d_in[3];
    const float* rpb   = (const float*)d_in[4];
    (void)in_sizes; (void)n_in; (void)out_size;

    cudaFuncSetAttribute(k_qkv,  cudaFuncAttributeMaxDynamicSharedMemorySize, SMEM_BYTES);
    cudaFuncSetAttribute(k_proj, cudaFuncAttributeMaxDynamicSharedMemorySize, SMEM_BYTES);

    k_qkv <<<dim3(9, NW), 128, SMEM_BYTES>>>(x, qkvw);
    k_attn<<<dim3(NHD, NW), 32>>>(rpb);
    k_proj<<<dim3(3, NW), 128, SMEM_BYTES>>>(projw, pb, (float*)d_out);
}

// round 9
// speedup vs baseline: 2.0363x; 1.5771x over previous
#include <cuda_runtime.h>
#include <cuda_bf16.h>
#include <cstdint>

typedef unsigned long long ull;

#define NW   4096
#define NHD  6
#define HD   32
#define CDIM 192
#define WS2  64

// smem tile layout (bf16, row pitch 200 => 400B rows, 16B aligned, ldmatrix conflict-free)
#define PITCH  200
#define OFF_AH 0
#define OFF_AL 51200
#define OFF_BH 102400
#define OFF_BL 128000
#define GEMM_SMEM 153600

// ---- scratch ----
__device__ float g_qkv[(size_t)3 * NW * NHD * WS2 * HD];   // [which][w][h][t][d]
__device__ float g_att[(size_t)NW * WS2 * CDIM];           // [w][t][h*32+d]

// ================= mma / ldmatrix helpers =================
__device__ __forceinline__ uint32_t smem_to_u32(const void* p) {
    uint32_t a;
    asm("{ .reg .u64 t; cvta.to.shared.u64 t, %1; cvt.u32.u64 %0, t; }" : "=r"(a) : "l"(p));
    return a;
}
__device__ __forceinline__ void ldsm4(uint32_t& r0, uint32_t& r1, uint32_t& r2, uint32_t& r3,
                                      uint32_t addr) {
    asm volatile("ldmatrix.sync.aligned.m8n8.x4.shared.b16 {%0,%1,%2,%3}, [%4];"
                 : "=r"(r0), "=r"(r1), "=r"(r2), "=r"(r3) : "r"(addr));
}
__device__ __forceinline__ void mma16816(float* c, uint32_t a0, uint32_t a1, uint32_t a2,
                                         uint32_t a3, uint32_t b0, uint32_t b1) {
    asm volatile("mma.sync.aligned.m16n8k16.row.col.f32.bf16.bf16.f32 "
                 "{%0,%1,%2,%3}, {%4,%5,%6,%7}, {%8,%9}, {%0,%1,%2,%3};"
                 : "+f"(c[0]), "+f"(c[1]), "+f"(c[2]), "+f"(c[3])
                 : "r"(a0), "r"(a1), "r"(a2), "r"(a3), "r"(b0), "r"(b1));
}

// ================= f32x2 helpers (attn) =================
__device__ __forceinline__ ull dup2(float a) {
    ull r; asm("mov.b64 %0, {%1, %1};" : "=l"(r) : "f"(a)); return r;
}
__device__ __forceinline__ void fma2(ull& d, ull a, ull b) {
    asm("fma.rn.f32x2 %0, %1, %2, %0;" : "+l"(d) : "l"(a), "l"(b));
}
__device__ __forceinline__ ull add2(ull a, ull b) {
    ull r; asm("add.rn.f32x2 %0, %1, %2;" : "=l"(r) : "l"(a), "l"(b)); return r;
}
__device__ __forceinline__ ull mul2(ull a, ull b) {
    ull r; asm("mul.rn.f32x2 %0, %1, %2;" : "=l"(r) : "l"(a), "l"(b)); return r;
}
__device__ __forceinline__ float2 unpk(ull v) {
    float2 f; asm("mov.b64 {%0, %1}, %2;" : "=f"(f.x), "=f"(f.y) : "l"(v)); return f;
}

// ================= staging: fp32 rows -> bf16 hi/lo smem tiles =================
__device__ __forceinline__ void cvt8(float4 v0, float4 v1, uint4& hi, uint4& lo) {
    __nv_bfloat162 h0 = __floats2bfloat162_rn(v0.x, v0.y);
    __nv_bfloat162 h1 = __floats2bfloat162_rn(v0.z, v0.w);
    __nv_bfloat162 h2 = __floats2bfloat162_rn(v1.x, v1.y);
    __nv_bfloat162 h3 = __floats2bfloat162_rn(v1.z, v1.w);
    float2 f0 = __bfloat1622float2(h0), f1 = __bfloat1622float2(h1);
    float2 f2 = __bfloat1622float2(h2), f3 = __bfloat1622float2(h3);
    __nv_bfloat162 l0 = __floats2bfloat162_rn(v0.x - f0.x, v0.y - f0.y);
    __nv_bfloat162 l1 = __floats2bfloat162_rn(v0.z - f1.x, v0.w - f1.y);
    __nv_bfloat162 l2 = __floats2bfloat162_rn(v1.x - f2.x, v1.y - f2.y);
    __nv_bfloat162 l3 = __floats2bfloat162_rn(v1.z - f3.x, v1.w - f3.y);
    hi = make_uint4(*(uint32_t*)&h0, *(uint32_t*)&h1, *(uint32_t*)&h2, *(uint32_t*)&h3);
    lo = make_uint4(*(uint32_t*)&l0, *(uint32_t*)&l1, *(uint32_t*)&l2, *(uint32_t*)&l3);
}

__device__ __forceinline__ void stage_rows(const float* __restrict__ src, int nrows,
                                           char* dh, char* dl, int tid) {
    int groups = nrows * 24;                // 24 groups of 8 floats per 192-row
    for (int idx = tid; idx < groups; idx += 128) {
        int r = idx / 24, g = idx - r * 24;
        const float4* p = (const float4*)(src + (size_t)r * CDIM + g * 8);
        uint4 hi, lo;
        cvt8(p[0], p[1], hi, lo);
        uint32_t o = (uint32_t)(r * PITCH + g * 8) * 2;
        *(uint4*)(dh + o) = hi;
        *(uint4*)(dl + o) = lo;
    }
}

// ================= warp mma core: 32x64 per warp over K=192, split-bf16 =================
__device__ __forceinline__ void mma_core(uint32_t sb, int warp, int lane, float acc[2][8][4]) {
#pragma unroll
    for (int mf = 0; mf < 2; ++mf)
#pragma unroll
        for (int nf = 0; nf < 8; ++nf)
#pragma unroll
            for (int j = 0; j < 4; ++j) acc[mf][nf][j] = 0.0f;

    const uint32_t aoff = (uint32_t)((warp * 32 + (lane & 15)) * PITCH + (lane >> 4) * 8) * 2;
    const uint32_t boff = (uint32_t)(((lane & 7) + ((lane >> 4) << 3)) * PITCH + ((lane >> 3) & 1) * 8) * 2;
    const uint32_t aAh = sb + OFF_AH + aoff, aAl = sb + OFF_AL + aoff;
    const uint32_t aBh = sb + OFF_BH + boff, aBl = sb + OFF_BL + boff;

#pragma unroll 2
    for (int kc = 0; kc < 12; ++kc) {
        uint32_t ko = kc * 32;              // 16 bf16 = 32 bytes
        uint32_t ah[2][4], al[2][4], bh[8][2], bl[8][2];
#pragma unroll
        for (int mf = 0; mf < 2; ++mf) {
            ldsm4(ah[mf][0], ah[mf][1], ah[mf][2], ah[mf][3], aAh + mf * (16 * PITCH * 2) + ko);
            ldsm4(al[mf][0], al[mf][1], al[mf][2], al[mf][3], aAl + mf * (16 * PITCH * 2) + ko);
        }
#pragma unroll
        for (int np = 0; np < 4; ++np) {
            ldsm4(bh[2 * np][0], bh[2 * np][1], bh[2 * np + 1][0], bh[2 * np + 1][1],
                  aBh + np * (16 * PITCH * 2) + ko);
            ldsm4(bl[2 * np][0], bl[2 * np][1], bl[2 * np + 1][0], bl[2 * np + 1][1],
                  aBl + np * (16 * PITCH * 2) + ko);
        }
#pragma unroll
        for (int mf = 0; mf < 2; ++mf)
#pragma unroll
            for (int nf = 0; nf < 8; ++nf) {
                mma16816(acc[mf][nf], ah[mf][0], ah[mf][1], ah[mf][2], ah[mf][3],
                         bh[nf][0], bh[nf][1]);
                mma16816(acc[mf][nf], ah[mf][0], ah[mf][1], ah[mf][2], ah[mf][3],
                         bl[nf][0], bl[nf][1]);
                mma16816(acc[mf][nf], al[mf][0], al[mf][1], al[mf][2], al[mf][3],
                         bh[nf][0], bh[nf][1]);
            }
    }
}

// ================= K1: QKV GEMM + window scatter =================
// grid(2048): 128 pixel rows per CTA; loop 9 N-tiles of qkv_w.
__global__ __launch_bounds__(128) void k_qkv(const float* __restrict__ x,
                                             const float* __restrict__ qkvw) {
    extern __shared__ char smem[];
    uint32_t sb = smem_to_u32(smem);
    int tid = threadIdx.x, mt = blockIdx.x;
    int warp = tid >> 5, lane = tid & 31;

    stage_rows(x + (size_t)mt * 128 * CDIM, 128, smem + OFF_AH, smem + OFF_AL, tid);

    for (int nt = 0; nt < 9; ++nt) {
        stage_rows(qkvw + (size_t)nt * 64 * CDIM, 64, smem + OFF_BH, smem + OFF_BL, tid);
        __syncthreads();

        float acc[2][8][4];
        mma_core(sb, warp, lane, acc);

        int which = nt / 3;
        int rem0 = (nt - which * 3) * 64;
        float s = (which == 0) ? 0.17677669529663687f : 1.0f;
        size_t plane = (size_t)which * NW * NHD * 2048;
#pragma unroll
        for (int mf = 0; mf < 2; ++mf)
#pragma unroll
            for (int half = 0; half < 2; ++half) {
                int p = mt * 128 + warp * 32 + mf * 16 + (lane >> 2) + half * 8;
                int b = p >> 16, y = (p >> 8) & 255, xc = p & 255;
                int w = (b << 10) | ((y >> 3) << 5) | (xc >> 3);
                int t = ((y & 7) << 3) | (xc & 7);
                size_t base = plane + ((size_t)w * NHD) * 2048 + t * 32;
#pragma unroll
                for (int nf = 0; nf < 8; ++nf) {
                    int rem = rem0 + nf * 8 + (lane & 3) * 2;
                    int h = rem >> 5, d = rem & 31;
                    *(float2*)(g_qkv + base + (size_t)h * 2048 + d) =
                        make_float2(acc[mf][nf][half * 2] * s, acc[mf][nf][half * 2 + 1] * s);
                }
            }
        __syncthreads();
    }
}

// ================= K2: windowed attention (VERBATIM from passing R6) =================
__global__ __launch_bounds__(32) void k_attn(const float* __restrict__ rpb) {
    __shared__ float ks[2048], vs[2048], bias_s[240];
    int h = blockIdx.x, w = blockIdx.y, lane = threadIdx.x;
    size_t base = ((size_t)(w * NHD + h)) << 11;
    const size_t plane = (size_t)NW * NHD * 2048;
    const float4* kp4 = (const float4*)(g_qkv + plane + base);
    const float4* vp4 = (const float4*)(g_qkv + 2 * plane + base);
#pragma unroll
    for (int u = 0; u < 16; ++u) {
        ((float4*)ks)[(u << 5) + lane] = kp4[(u << 5) + lane];
        ((float4*)vs)[(u << 5) + lane] = vp4[(u << 5) + lane];
    }
    for (int i = lane; i < 225; i += 32) bias_s[i] = rpb[i * NHD + h];
    __syncthreads();

    int q0 = lane << 1, q1 = q0 + 1;
    ull qr0[16], qr1[16];
    const ull* qp = (const ull*)(g_qkv + base + (size_t)q0 * HD);
#pragma unroll
    for (int i = 0; i < 16; ++i) { qr0[i] = qp[i]; qr1[i] = qp[16 + i]; }

    int q0i = q0 >> 3, q0j = q0 & 7;
    int q1i = q1 >> 3, q1j = q1 & 7;
    ull acc0[16], acc1[16];
#pragma unroll
    for (int i = 0; i < 16; ++i) { acc0[i] = 0ull; acc1[i] = 0ull; }
    float sum0 = 0.0f, sum1 = 0.0f;

#pragma unroll 4
    for (int kk = 0; kk < 64; ++kk) {
        const ull* kr = (const ull*)(ks + (kk << 5));
        ull e00 = 0ull, e01 = 0ull, e10 = 0ull, e11 = 0ull;
#pragma unroll
        for (int i = 0; i < 8; ++i) {
            ull k0 = kr[2 * i], k1 = kr[2 * i + 1];
            fma2(e00, qr0[2 * i], k0);
            fma2(e01, qr0[2 * i + 1], k1);
            fma2(e10, qr1[2 * i], k0);
            fma2(e11, qr1[2 * i + 1], k1);
        }
        int ki = kk >> 3, kj = kk & 7;
        int bidx = (7 - ki) * 15 + (7 - kj);
        float2 f0 = unpk(add2(e00, e01));
        float2 f1 = unpk(add2(e10, e11));
        float p0 = __expf(f0.x + f0.y + bias_s[bidx + q0i * 15 + q0j]);
        float p1 = __expf(f1.x + f1.y + bias_s[bidx + q1i * 15 + q1j]);
        sum0 += p0; sum1 += p1;
        ull pv0 = dup2(p0), pv1 = dup2(p1);
        const ull* vr = (const ull*)(vs + (kk << 5));
#pragma unroll
        for (int i = 0; i < 16; ++i) {
            ull vv = vr[i];
            fma2(acc0[i], pv0, vv);
            fma2(acc1[i], pv1, vv);
        }
    }

    ull inv0 = dup2(1.0f / sum0), inv1 = dup2(1.0f / sum1);
    ull* op0 = (ull*)(g_att + ((size_t)w * WS2 + q0) * CDIM + h * HD);
    ull* op1 = (ull*)(g_att + ((size_t)w * WS2 + q1) * CDIM + h * HD);
#pragma unroll
    for (int i = 0; i < 16; ++i) {
        op0[i] = mul2(acc0[i], inv0);
        op1[i] = mul2(acc1[i], inv1);
    }
}

// ================= K3: proj GEMM + bias + pixel scatter =================
// grid(2048): 128 g_att rows per CTA; loop 3 N-tiles of proj_w.
__global__ __launch_bounds__(128) void k_proj(const float* __restrict__ projw,
                                              const float* __restrict__ pb,
                                              float* __restrict__ out) {
    extern __shared__ char smem[];
    uint32_t sb = smem_to_u32(smem);
    int tid = threadIdx.x, mt = blockIdx.x;
    int warp = tid >> 5, lane = tid & 31;

    stage_rows(g_att + (size_t)mt * 128 * CDIM, 128, smem + OFF_AH, smem + OFF_AL, tid);

    for (int nt = 0; nt < 3; ++nt) {
        stage_rows(projw + (size_t)nt * 64 * CDIM, 64, smem + OFF_BH, smem + OFF_BL, tid);
        __syncthreads();

        float acc[2][8][4];
        mma_core(sb, warp, lane, acc);

#pragma unroll
        for (int mf = 0; mf < 2; ++mf)
#pragma unroll
            for (int half = 0; half < 2; ++half) {
                int p = mt * 128 + warp * 32 + mf * 16 + (lane >> 2) + half * 8;
                int w = p >> 6, t = p & 63;
                int b = w >> 10, wh = (w >> 5) & 31, ww = w & 31;
                int ri = t >> 3, ci = t & 7;
                size_t pix = (size_t)((b << 8) + (wh << 3) + ri) * 256 + (ww << 3) + ci;
                float* o = out + pix * CDIM;
#pragma unroll
                for (int nf = 0; nf < 8; ++nf) {
                    int oc = nt * 64 + nf * 8 + (lane & 3) * 2;
                    float2 bias = *(const float2*)(pb + oc);
                    *(float2*)(o + oc) = make_float2(acc[mf][nf][half * 2] + bias.x,
                                                     acc[mf][nf][half * 2 + 1] + bias.y);
                }
            }
        __syncthreads();
    }
}

// ================= launch =================
extern "C" void kernel_launch(void* const* d_in, const int* in_sizes, int n_in,
                              void* d_out, int out_size) {
    const float* x     = (const float*)d_in[0];
    const float* qkvw  = (const float*)d_in[1];
    const float* projw = (const float*)d_in[2];
    const float* pb    = (const float*)d_in[3];
    const float* rpb   = (const float*)d_in[4];
    (void)in_sizes; (void)n_in; (void)out_size;

    cudaFuncSetAttribute(k_qkv,  cudaFuncAttributeMaxDynamicSharedMemorySize, GEMM_SMEM);
    cudaFuncSetAttribute(k_proj, cudaFuncAttributeMaxDynamicSharedMemorySize, GEMM_SMEM);

    k_qkv <<<2048, 128, GEMM_SMEM>>>(x, qkvw);
    k_attn<<<dim3(NHD, NW), 32>>>(rpb);
    k_proj<<<2048, 128, GEMM_SMEM>>>(projw, pb, (float*)d_out);
}

// round 10
// speedup vs baseline: 2.2056x; 1.0832x over previous
#include <cuda_runtime.h>
#include <cuda_bf16.h>
#include <cstdint>

typedef unsigned long long ull;

#define NW   4096
#define NHD  6
#define HD   32
#define CDIM 192
#define WS2  64

// smem tile layout (bf16, row pitch 200 elems => 400B rows, ldmatrix conflict-free)
#define PITCH  200
#define OFF_AH 0
#define OFF_AL 51200
#define OFF_BH 102400
#define OFF_BL 128000
#define GEMM_SMEM 153600

// ---- scratch ----
__device__ float g_qkv[(size_t)3 * NW * NHD * WS2 * HD];   // [which][w][h][t][d]
__device__ float g_att[(size_t)NW * WS2 * CDIM];           // [w][t][h*32+d]
__device__ __nv_bfloat16 g_wqh[576 * 192], g_wql[576 * 192];  // qkv weights hi/lo (q rows pre-scaled)
__device__ __nv_bfloat16 g_wph[192 * 192], g_wpl[192 * 192];  // proj weights hi/lo

// ================= mma / ldmatrix helpers =================
__device__ __forceinline__ uint32_t smem_to_u32(const void* p) {
    uint32_t a;
    asm("{ .reg .u64 t; cvta.to.shared.u64 t, %1; cvt.u32.u64 %0, t; }" : "=r"(a) : "l"(p));
    return a;
}
__device__ __forceinline__ void ldsm4(uint32_t& r0, uint32_t& r1, uint32_t& r2, uint32_t& r3,
                                      uint32_t addr) {
    asm volatile("ldmatrix.sync.aligned.m8n8.x4.shared.b16 {%0,%1,%2,%3}, [%4];"
                 : "=r"(r0), "=r"(r1), "=r"(r2), "=r"(r3) : "r"(addr));
}
__device__ __forceinline__ void mma16816(float* c, uint32_t a0, uint32_t a1, uint32_t a2,
                                         uint32_t a3, uint32_t b0, uint32_t b1) {
    asm volatile("mma.sync.aligned.m16n8k16.row.col.f32.bf16.bf16.f32 "
                 "{%0,%1,%2,%3}, {%4,%5,%6,%7}, {%8,%9}, {%0,%1,%2,%3};"
                 : "+f"(c[0]), "+f"(c[1]), "+f"(c[2]), "+f"(c[3])
                 : "r"(a0), "r"(a1), "r"(a2), "r"(a3), "r"(b0), "r"(b1));
}

// ================= f32x2 helpers (attn) =================
__device__ __forceinline__ ull dup2(float a) {
    ull r; asm("mov.b64 %0, {%1, %1};" : "=l"(r) : "f"(a)); return r;
}
__device__ __forceinline__ void fma2(ull& d, ull a, ull b) {
    asm("fma.rn.f32x2 %0, %1, %2, %0;" : "+l"(d) : "l"(a), "l"(b));
}
__device__ __forceinline__ ull add2(ull a, ull b) {
    ull r; asm("add.rn.f32x2 %0, %1, %2;" : "=l"(r) : "l"(a), "l"(b)); return r;
}
__device__ __forceinline__ ull mul2(ull a, ull b) {
    ull r; asm("mul.rn.f32x2 %0, %1, %2;" : "=l"(r) : "l"(a), "l"(b)); return r;
}
__device__ __forceinline__ float2 unpk(ull v) {
    float2 f; asm("mov.b64 {%0, %1}, %2;" : "=f"(f.x), "=f"(f.y) : "l"(v)); return f;
}

// ================= prep: weights fp32 -> bf16 hi/lo (q rows pre-scaled) =================
__global__ void k_prep(const float* __restrict__ qkvw, const float* __restrict__ projw) {
    int o = blockIdx.x, c = threadIdx.x;
    if (o < 576) {
        float v = qkvw[o * 192 + c];
        if (o < 192) v *= 0.17677669529663687f;
        __nv_bfloat16 h = __float2bfloat16(v);
        g_wqh[o * 192 + c] = h;
        g_wql[o * 192 + c] = __float2bfloat16(v - __bfloat162float(h));
    } else {
        int oo = o - 576;
        float v = projw[oo * 192 + c];
        __nv_bfloat16 h = __float2bfloat16(v);
        g_wph[oo * 192 + c] = h;
        g_wpl[oo * 192 + c] = __float2bfloat16(v - __bfloat162float(h));
    }
}

// ================= staging =================
__device__ __forceinline__ void cvt8(float4 v0, float4 v1, uint4& hi, uint4& lo) {
    __nv_bfloat162 h0 = __floats2bfloat162_rn(v0.x, v0.y);
    __nv_bfloat162 h1 = __floats2bfloat162_rn(v0.z, v0.w);
    __nv_bfloat162 h2 = __floats2bfloat162_rn(v1.x, v1.y);
    __nv_bfloat162 h3 = __floats2bfloat162_rn(v1.z, v1.w);
    float2 f0 = __bfloat1622float2(h0), f1 = __bfloat1622float2(h1);
    float2 f2 = __bfloat1622float2(h2), f3 = __bfloat1622float2(h3);
    __nv_bfloat162 l0 = __floats2bfloat162_rn(v0.x - f0.x, v0.y - f0.y);
    __nv_bfloat162 l1 = __floats2bfloat162_rn(v0.z - f1.x, v0.w - f1.y);
    __nv_bfloat162 l2 = __floats2bfloat162_rn(v1.x - f2.x, v1.y - f2.y);
    __nv_bfloat162 l3 = __floats2bfloat162_rn(v1.z - f3.x, v1.w - f3.y);
    hi = make_uint4(*(uint32_t*)&h0, *(uint32_t*)&h1, *(uint32_t*)&h2, *(uint32_t*)&h3);
    lo = make_uint4(*(uint32_t*)&l0, *(uint32_t*)&l1, *(uint32_t*)&l2, *(uint32_t*)&l3);
}

// fp32 source -> split hi/lo into smem (A tiles)
__device__ __forceinline__ void stage_rows_f32(const float* __restrict__ src, int nrows,
                                               char* dh, char* dl, int tid) {
    int groups = nrows * 24;
    for (int idx = tid; idx < groups; idx += 256) {
        int r = idx / 24, g = idx - r * 24;
        const float4* p = (const float4*)(src + (size_t)r * CDIM + g * 8);
        uint4 hi, lo;
        cvt8(p[0], p[1], hi, lo);
        uint32_t o = (uint32_t)(r * PITCH + g * 8) * 2;
        *(uint4*)(dh + o) = hi;
        *(uint4*)(dl + o) = lo;
    }
}

// pre-split bf16 source -> copy into smem (B tiles)
__device__ __forceinline__ void stage_rows_bf16(const __nv_bfloat16* __restrict__ sh,
                                                const __nv_bfloat16* __restrict__ sl,
                                                int nrows, char* dh, char* dl, int tid) {
    int groups = nrows * 24;
    for (int idx = tid; idx < groups; idx += 256) {
        int r = idx / 24, g = idx - r * 24;
        uint32_t o = (uint32_t)(r * PITCH + g * 8) * 2;
        *(uint4*)(dh + o) = *(const uint4*)(sh + (size_t)r * CDIM + g * 8);
        *(uint4*)(dl + o) = *(const uint4*)(sl + (size_t)r * CDIM + g * 8);
    }
}

// ================= warp mma core: 16x64 per warp over K=192, split-bf16 =================
__device__ __forceinline__ void mma_core(uint32_t sb, int warp, int lane, float acc[8][4]) {
#pragma unroll
    for (int nf = 0; nf < 8; ++nf)
#pragma unroll
        for (int j = 0; j < 4; ++j) acc[nf][j] = 0.0f;

    const uint32_t aoff = (uint32_t)((warp * 16 + (lane & 15)) * PITCH + (lane >> 4) * 8) * 2;
    const uint32_t boff = (uint32_t)(((lane & 7) + ((lane >> 4) << 3)) * PITCH + ((lane >> 3) & 1) * 8) * 2;
    const uint32_t aAh = sb + OFF_AH + aoff, aAl = sb + OFF_AL + aoff;
    const uint32_t aBh = sb + OFF_BH + boff, aBl = sb + OFF_BL + boff;

#pragma unroll 2
    for (int kc = 0; kc < 12; ++kc) {
        uint32_t ko = kc * 32;
        uint32_t ah[4], al[4], bh[8][2], bl[8][2];
        ldsm4(ah[0], ah[1], ah[2], ah[3], aAh + ko);
        ldsm4(al[0], al[1], al[2], al[3], aAl + ko);
#pragma unroll
        for (int np = 0; np < 4; ++np) {
            ldsm4(bh[2 * np][0], bh[2 * np][1], bh[2 * np + 1][0], bh[2 * np + 1][1],
                  aBh + np * (16 * PITCH * 2) + ko);
            ldsm4(bl[2 * np][0], bl[2 * np][1], bl[2 * np + 1][0], bl[2 * np + 1][1],
                  aBl + np * (16 * PITCH * 2) + ko);
        }
#pragma unroll
        for (int nf = 0; nf < 8; ++nf) {
            mma16816(acc[nf], ah[0], ah[1], ah[2], ah[3], bh[nf][0], bh[nf][1]);
            mma16816(acc[nf], ah[0], ah[1], ah[2], ah[3], bl[nf][0], bl[nf][1]);
            mma16816(acc[nf], al[0], al[1], al[2], al[3], bh[nf][0], bh[nf][1]);
        }
    }
}

// ================= K1: QKV GEMM + window scatter =================
// grid(2048): 128 pixel rows per CTA; 256 thr (8 warps x 16 rows); loop 9 N-tiles.
__global__ __launch_bounds__(256) void k_qkv(const float* __restrict__ x) {
    extern __shared__ char smem[];
    uint32_t sb = smem_to_u32(smem);
    int tid = threadIdx.x, mt = blockIdx.x;
    int warp = tid >> 5, lane = tid & 31;

    stage_rows_f32(x + (size_t)mt * 128 * CDIM, 128, smem + OFF_AH, smem + OFF_AL, tid);

    for (int nt = 0; nt < 9; ++nt) {
        stage_rows_bf16(g_wqh + (size_t)nt * 64 * CDIM, g_wql + (size_t)nt * 64 * CDIM,
                        64, smem + OFF_BH, smem + OFF_BL, tid);
        __syncthreads();

        float acc[8][4];
        mma_core(sb, warp, lane, acc);

        int which = nt / 3;
        int rem0 = (nt - which * 3) * 64;
        size_t plane = (size_t)which * NW * NHD * 2048;
#pragma unroll
        for (int half = 0; half < 2; ++half) {
            int p = mt * 128 + warp * 16 + (lane >> 2) + half * 8;
            int b = p >> 16, y = (p >> 8) & 255, xc = p & 255;
            int w = (b << 10) | ((y >> 3) << 5) | (xc >> 3);
            int t = ((y & 7) << 3) | (xc & 7);
            size_t base = plane + ((size_t)w * NHD) * 2048 + t * 32;
#pragma unroll
            for (int nf = 0; nf < 8; ++nf) {
                int rem = rem0 + nf * 8 + (lane & 3) * 2;
                int h = rem >> 5, d = rem & 31;
                *(float2*)(g_qkv + base + (size_t)h * 2048 + d) =
                    make_float2(acc[nf][half * 2], acc[nf][half * 2 + 1]);
            }
        }
        __syncthreads();
    }
}

// ================= K2: windowed attention (VERBATIM passing version) =================
__global__ __launch_bounds__(32) void k_attn(const float* __restrict__ rpb) {
    __shared__ float ks[2048], vs[2048], bias_s[240];
    int h = blockIdx.x, w = blockIdx.y, lane = threadIdx.x;
    size_t base = ((size_t)(w * NHD + h)) << 11;
    const size_t plane = (size_t)NW * NHD * 2048;
    const float4* kp4 = (const float4*)(g_qkv + plane + base);
    const float4* vp4 = (const float4*)(g_qkv + 2 * plane + base);
#pragma unroll
    for (int u = 0; u < 16; ++u) {
        ((float4*)ks)[(u << 5) + lane] = kp4[(u << 5) + lane];
        ((float4*)vs)[(u << 5) + lane] = vp4[(u << 5) + lane];
    }
    for (int i = lane; i < 225; i += 32) bias_s[i] = rpb[i * NHD + h];
    __syncthreads();

    int q0 = lane << 1, q1 = q0 + 1;
    ull qr0[16], qr1[16];
    const ull* qp = (const ull*)(g_qkv + base + (size_t)q0 * HD);
#pragma unroll
    for (int i = 0; i < 16; ++i) { qr0[i] = qp[i]; qr1[i] = qp[16 + i]; }

    int q0i = q0 >> 3, q0j = q0 & 7;
    int q1i = q1 >> 3, q1j = q1 & 7;
    ull acc0[16], acc1[16];
#pragma unroll
    for (int i = 0; i < 16; ++i) { acc0[i] = 0ull; acc1[i] = 0ull; }
    float sum0 = 0.0f, sum1 = 0.0f;

#pragma unroll 4
    for (int kk = 0; kk < 64; ++kk) {
        const ull* kr = (const ull*)(ks + (kk << 5));
        ull e00 = 0ull, e01 = 0ull, e10 = 0ull, e11 = 0ull;
#pragma unroll
        for (int i = 0; i < 8; ++i) {
            ull k0 = kr[2 * i], k1 = kr[2 * i + 1];
            fma2(e00, qr0[2 * i], k0);
            fma2(e01, qr0[2 * i + 1], k1);
            fma2(e10, qr1[2 * i], k0);
            fma2(e11, qr1[2 * i + 1], k1);
        }
        int ki = kk >> 3, kj = kk & 7;
        int bidx = (7 - ki) * 15 + (7 - kj);
        float2 f0 = unpk(add2(e00, e01));
        float2 f1 = unpk(add2(e10, e11));
        float p0 = __expf(f0.x + f0.y + bias_s[bidx + q0i * 15 + q0j]);
        float p1 = __expf(f1.x + f1.y + bias_s[bidx + q1i * 15 + q1j]);
        sum0 += p0; sum1 += p1;
        ull pv0 = dup2(p0), pv1 = dup2(p1);
        const ull* vr = (const ull*)(vs + (kk << 5));
#pragma unroll
        for (int i = 0; i < 16; ++i) {
            ull vv = vr[i];
            fma2(acc0[i], pv0, vv);
            fma2(acc1[i], pv1, vv);
        }
    }

    ull inv0 = dup2(1.0f / sum0), inv1 = dup2(1.0f / sum1);
    ull* op0 = (ull*)(g_att + ((size_t)w * WS2 + q0) * CDIM + h * HD);
    ull* op1 = (ull*)(g_att + ((size_t)w * WS2 + q1) * CDIM + h * HD);
#pragma unroll
    for (int i = 0; i < 16; ++i) {
        op0[i] = mul2(acc0[i], inv0);
        op1[i] = mul2(acc1[i], inv1);
    }
}

// ================= K3: proj GEMM + bias + pixel scatter =================
// grid(2048): 128 g_att rows per CTA; 256 thr; loop 3 N-tiles.
__global__ __launch_bounds__(256) void k_proj(const float* __restrict__ pb,
                                              float* __restrict__ out) {
    extern __shared__ char smem[];
    uint32_t sb = smem_to_u32(smem);
    int tid = threadIdx.x, mt = blockIdx.x;
    int warp = tid >> 5, lane = tid & 31;

    stage_rows_f32(g_att + (size_t)mt * 128 * CDIM, 128, smem + OFF_AH, smem + OFF_AL, tid);

    for (int nt = 0; nt < 3; ++nt) {
        stage_rows_bf16(g_wph + (size_t)nt * 64 * CDIM, g_wpl + (size_t)nt * 64 * CDIM,
                        64, smem + OFF_BH, smem + OFF_BL, tid);
        __syncthreads();

        float acc[8][4];
        mma_core(sb, warp, lane, acc);

#pragma unroll
        for (int half = 0; half < 2; ++half) {
            int p = mt * 128 + warp * 16 + (lane >> 2) + half * 8;
            int w = p >> 6, t = p & 63;
            int b = w >> 10, wh = (w >> 5) & 31, ww = w & 31;
            int ri = t >> 3, ci = t & 7;
            size_t pix = (size_t)((b << 8) + (wh << 3) + ri) * 256 + (ww << 3) + ci;
            float* o = out + pix * CDIM;
#pragma unroll
            for (int nf = 0; nf < 8; ++nf) {
                int oc = nt * 64 + nf * 8 + (lane & 3) * 2;
                float2 bias = *(const float2*)(pb + oc);
                *(float2*)(o + oc) = make_float2(acc[nf][half * 2] + bias.x,
                                                 acc[nf][half * 2 + 1] + bias.y);
            }
        }
        __syncthreads();
    }
}

// ================= launch =================
extern "C" void kernel_launch(void* const* d_in, const int* in_sizes, int n_in,
                              void* d_out, int out_size) {
    const float* x     = (const float*)d_in[0];
    const float* qkvw  = (const float*)d_in[1];
    const float* projw = (const float*)d_in[2];
    const float* pb    = (const float*)d_in[3];
    const float* rpb   = (const float*)d_in[4];
    (void)in_sizes; (void)n_in; (void)out_size;

    cudaFuncSetAttribute(k_qkv,  cudaFuncAttributeMaxDynamicSharedMemorySize, GEMM_SMEM);
    cudaFuncSetAttribute(k_proj, cudaFuncAttributeMaxDynamicSharedMemorySize, GEMM_SMEM);

    k_prep<<<768, 192>>>(qkvw, projw);
    k_qkv <<<2048, 256, GEMM_SMEM>>>(x);
    k_attn<<<dim3(NHD, NW), 32>>>(rpb);
    k_proj<<<2048, 256, GEMM_SMEM>>>(pb, (float*)d_out);
}

// round 11
// speedup vs baseline: 2.2319x; 1.0119x over previous
#include <cuda_runtime.h>
#include <cuda_bf16.h>
#include <cstdint>

typedef unsigned long long ull;

#define NW   4096
#define NHD  6
#define HD   32
#define CDIM 192
#define WS2  64

// smem tile layout (bf16, row pitch 200 elems => 400B rows, ldmatrix conflict-free)
#define PITCH  200
#define OFF_AH 0
#define OFF_AL 51200
#define OFF_BH 102400
#define OFF_BL 128000
#define GEMM_SMEM 153600

// ---- scratch ----
__device__ float g_qkv[(size_t)3 * NW * NHD * WS2 * HD];   // [which][w][h][t][d]
__device__ float g_att[(size_t)NW * WS2 * CDIM];           // [w][t][h*32+d]
__device__ __nv_bfloat16 g_wqh[576 * 192], g_wql[576 * 192];  // qkv weights hi/lo (q rows pre-scaled)
__device__ __nv_bfloat16 g_wph[192 * 192], g_wpl[192 * 192];  // proj weights hi/lo

// ================= mma / ldmatrix helpers =================
__device__ __forceinline__ uint32_t smem_to_u32(const void* p) {
    uint32_t a;
    asm("{ .reg .u64 t; cvta.to.shared.u64 t, %1; cvt.u32.u64 %0, t; }" : "=r"(a) : "l"(p));
    return a;
}
__device__ __forceinline__ void ldsm4(uint32_t& r0, uint32_t& r1, uint32_t& r2, uint32_t& r3,
                                      uint32_t addr) {
    asm volatile("ldmatrix.sync.aligned.m8n8.x4.shared.b16 {%0,%1,%2,%3}, [%4];"
                 : "=r"(r0), "=r"(r1), "=r"(r2), "=r"(r3) : "r"(addr));
}
__device__ __forceinline__ void mma16816(float* c, uint32_t a0, uint32_t a1, uint32_t a2,
                                         uint32_t a3, uint32_t b0, uint32_t b1) {
    asm volatile("mma.sync.aligned.m16n8k16.row.col.f32.bf16.bf16.f32 "
                 "{%0,%1,%2,%3}, {%4,%5,%6,%7}, {%8,%9}, {%0,%1,%2,%3};"
                 : "+f"(c[0]), "+f"(c[1]), "+f"(c[2]), "+f"(c[3])
                 : "r"(a0), "r"(a1), "r"(a2), "r"(a3), "r"(b0), "r"(b1));
}

// ================= f32x2 helpers (attn) =================
__device__ __forceinline__ ull dup2(float a) {
    ull r; asm("mov.b64 %0, {%1, %1};" : "=l"(r) : "f"(a)); return r;
}
__device__ __forceinline__ void fma2(ull& d, ull a, ull b) {
    asm("fma.rn.f32x2 %0, %1, %2, %0;" : "+l"(d) : "l"(a), "l"(b));
}
__device__ __forceinline__ ull add2(ull a, ull b) {
    ull r; asm("add.rn.f32x2 %0, %1, %2;" : "=l"(r) : "l"(a), "l"(b)); return r;
}
__device__ __forceinline__ ull mul2(ull a, ull b) {
    ull r; asm("mul.rn.f32x2 %0, %1, %2;" : "=l"(r) : "l"(a), "l"(b)); return r;
}
__device__ __forceinline__ float2 unpk(ull v) {
    float2 f; asm("mov.b64 {%0, %1}, %2;" : "=f"(f.x), "=f"(f.y) : "l"(v)); return f;
}

// ================= prep: weights fp32 -> bf16 hi/lo (q rows pre-scaled) =================
__global__ void k_prep(const float* __restrict__ qkvw, const float* __restrict__ projw) {
    int o = blockIdx.x, c = threadIdx.x;
    if (o < 576) {
        float v = qkvw[o * 192 + c];
        if (o < 192) v *= 0.17677669529663687f;
        __nv_bfloat16 h = __float2bfloat16(v);
        g_wqh[o * 192 + c] = h;
        g_wql[o * 192 + c] = __float2bfloat16(v - __bfloat162float(h));
    } else {
        int oo = o - 576;
        float v = projw[oo * 192 + c];
        __nv_bfloat16 h = __float2bfloat16(v);
        g_wph[oo * 192 + c] = h;
        g_wpl[oo * 192 + c] = __float2bfloat16(v - __bfloat162float(h));
    }
}

// ================= staging =================
__device__ __forceinline__ void cvt8(float4 v0, float4 v1, uint4& hi, uint4& lo) {
    __nv_bfloat162 h0 = __floats2bfloat162_rn(v0.x, v0.y);
    __nv_bfloat162 h1 = __floats2bfloat162_rn(v0.z, v0.w);
    __nv_bfloat162 h2 = __floats2bfloat162_rn(v1.x, v1.y);
    __nv_bfloat162 h3 = __floats2bfloat162_rn(v1.z, v1.w);
    float2 f0 = __bfloat1622float2(h0), f1 = __bfloat1622float2(h1);
    float2 f2 = __bfloat1622float2(h2), f3 = __bfloat1622float2(h3);
    __nv_bfloat162 l0 = __floats2bfloat162_rn(v0.x - f0.x, v0.y - f0.y);
    __nv_bfloat162 l1 = __floats2bfloat162_rn(v0.z - f1.x, v0.w - f1.y);
    __nv_bfloat162 l2 = __floats2bfloat162_rn(v1.x - f2.x, v1.y - f2.y);
    __nv_bfloat162 l3 = __floats2bfloat162_rn(v1.z - f3.x, v1.w - f3.y);
    hi = make_uint4(*(uint32_t*)&h0, *(uint32_t*)&h1, *(uint32_t*)&h2, *(uint32_t*)&h3);
    lo = make_uint4(*(uint32_t*)&l0, *(uint32_t*)&l1, *(uint32_t*)&l2, *(uint32_t*)&l3);
}

// fp32 source -> split hi/lo into smem (A tiles)
__device__ __forceinline__ void stage_rows_f32(const float* __restrict__ src, int nrows,
                                               char* dh, char* dl, int tid) {
    int groups = nrows * 24;
    for (int idx = tid; idx < groups; idx += 256) {
        int r = idx / 24, g = idx - r * 24;
        const float4* p = (const float4*)(src + (size_t)r * CDIM + g * 8);
        uint4 hi, lo;
        cvt8(p[0], p[1], hi, lo);
        uint32_t o = (uint32_t)(r * PITCH + g * 8) * 2;
        *(uint4*)(dh + o) = hi;
        *(uint4*)(dl + o) = lo;
    }
}

// pre-split bf16 source -> copy into smem (B tiles)
__device__ __forceinline__ void stage_rows_bf16(const __nv_bfloat16* __restrict__ sh,
                                                const __nv_bfloat16* __restrict__ sl,
                                                int nrows, char* dh, char* dl, int tid) {
    int groups = nrows * 24;
    for (int idx = tid; idx < groups; idx += 256) {
        int r = idx / 24, g = idx - r * 24;
        uint32_t o = (uint32_t)(r * PITCH + g * 8) * 2;
        *(uint4*)(dh + o) = *(const uint4*)(sh + (size_t)r * CDIM + g * 8);
        *(uint4*)(dl + o) = *(const uint4*)(sl + (size_t)r * CDIM + g * 8);
    }
}

// ================= warp mma core: 16x64 per warp over K=192, split-bf16 =================
__device__ __forceinline__ void mma_core(uint32_t sb, int warp, int lane, float acc[8][4]) {
#pragma unroll
    for (int nf = 0; nf < 8; ++nf)
#pragma unroll
        for (int j = 0; j < 4; ++j) acc[nf][j] = 0.0f;

    const uint32_t aoff = (uint32_t)((warp * 16 + (lane & 15)) * PITCH + (lane >> 4) * 8) * 2;
    const uint32_t boff = (uint32_t)(((lane & 7) + ((lane >> 4) << 3)) * PITCH + ((lane >> 3) & 1) * 8) * 2;
    const uint32_t aAh = sb + OFF_AH + aoff, aAl = sb + OFF_AL + aoff;
    const uint32_t aBh = sb + OFF_BH + boff, aBl = sb + OFF_BL + boff;

#pragma unroll 2
    for (int kc = 0; kc < 12; ++kc) {
        uint32_t ko = kc * 32;
        uint32_t ah[4], al[4], bh[8][2], bl[8][2];
        ldsm4(ah[0], ah[1], ah[2], ah[3], aAh + ko);
        ldsm4(al[0], al[1], al[2], al[3], aAl + ko);
#pragma unroll
        for (int np = 0; np < 4; ++np) {
            ldsm4(bh[2 * np][0], bh[2 * np][1], bh[2 * np + 1][0], bh[2 * np + 1][1],
                  aBh + np * (16 * PITCH * 2) + ko);
            ldsm4(bl[2 * np][0], bl[2 * np][1], bl[2 * np + 1][0], bl[2 * np + 1][1],
                  aBl + np * (16 * PITCH * 2) + ko);
        }
#pragma unroll
        for (int nf = 0; nf < 8; ++nf) {
            mma16816(acc[nf], ah[0], ah[1], ah[2], ah[3], bh[nf][0], bh[nf][1]);
            mma16816(acc[nf], ah[0], ah[1], ah[2], ah[3], bl[nf][0], bl[nf][1]);
            mma16816(acc[nf], al[0], al[1], al[2], al[3], bh[nf][0], bh[nf][1]);
        }
    }
}

// ================= K1: QKV GEMM + window scatter =================
// grid(2048): 128 pixel rows per CTA; 256 thr (8 warps x 16 rows); loop 9 N-tiles.
__global__ __launch_bounds__(256) void k_qkv(const float* __restrict__ x) {
    extern __shared__ char smem[];
    uint32_t sb = smem_to_u32(smem);
    int tid = threadIdx.x, mt = blockIdx.x;
    int warp = tid >> 5, lane = tid & 31;

    stage_rows_f32(x + (size_t)mt * 128 * CDIM, 128, smem + OFF_AH, smem + OFF_AL, tid);

    for (int nt = 0; nt < 9; ++nt) {
        stage_rows_bf16(g_wqh + (size_t)nt * 64 * CDIM, g_wql + (size_t)nt * 64 * CDIM,
                        64, smem + OFF_BH, smem + OFF_BL, tid);
        __syncthreads();

        float acc[8][4];
        mma_core(sb, warp, lane, acc);

        int which = nt / 3;
        int rem0 = (nt - which * 3) * 64;
        size_t plane = (size_t)which * NW * NHD * 2048;
#pragma unroll
        for (int half = 0; half < 2; ++half) {
            int p = mt * 128 + warp * 16 + (lane >> 2) + half * 8;
            int b = p >> 16, y = (p >> 8) & 255, xc = p & 255;
            int w = (b << 10) | ((y >> 3) << 5) | (xc >> 3);
            int t = ((y & 7) << 3) | (xc & 7);
            size_t base = plane + ((size_t)w * NHD) * 2048 + t * 32;
#pragma unroll
            for (int nf = 0; nf < 8; ++nf) {
                int rem = rem0 + nf * 8 + (lane & 3) * 2;
                int h = rem >> 5, d = rem & 31;
                *(float2*)(g_qkv + base + (size_t)h * 2048 + d) =
                    make_float2(acc[nf][half * 2], acc[nf][half * 2 + 1]);
            }
        }
        __syncthreads();
    }
}

// ================= K2: windowed attention (VERBATIM passing version) =================
__global__ __launch_bounds__(32) void k_attn(const float* __restrict__ rpb) {
    __shared__ float ks[2048], vs[2048], bias_s[240];
    int h = blockIdx.x, w = blockIdx.y, lane = threadIdx.x;
    size_t base = ((size_t)(w * NHD + h)) << 11;
    const size_t plane = (size_t)NW * NHD * 2048;
    const float4* kp4 = (const float4*)(g_qkv + plane + base);
    const float4* vp4 = (const float4*)(g_qkv + 2 * plane + base);
#pragma unroll
    for (int u = 0; u < 16; ++u) {
        ((float4*)ks)[(u << 5) + lane] = kp4[(u << 5) + lane];
        ((float4*)vs)[(u << 5) + lane] = vp4[(u << 5) + lane];
    }
    for (int i = lane; i < 225; i += 32) bias_s[i] = rpb[i * NHD + h];
    __syncthreads();

    int q0 = lane << 1, q1 = q0 + 1;
    ull qr0[16], qr1[16];
    const ull* qp = (const ull*)(g_qkv + base + (size_t)q0 * HD);
#pragma unroll
    for (int i = 0; i < 16; ++i) { qr0[i] = qp[i]; qr1[i] = qp[16 + i]; }

    int q0i = q0 >> 3, q0j = q0 & 7;
    int q1i = q1 >> 3, q1j = q1 & 7;
    ull acc0[16], acc1[16];
#pragma unroll
    for (int i = 0; i < 16; ++i) { acc0[i] = 0ull; acc1[i] = 0ull; }
    float sum0 = 0.0f, sum1 = 0.0f;

#pragma unroll 4
    for (int kk = 0; kk < 64; ++kk) {
        const ull* kr = (const ull*)(ks + (kk << 5));
        ull e00 = 0ull, e01 = 0ull, e10 = 0ull, e11 = 0ull;
#pragma unroll
        for (int i = 0; i < 8; ++i) {
            ull k0 = kr[2 * i], k1 = kr[2 * i + 1];
            fma2(e00, qr0[2 * i], k0);
            fma2(e01, qr0[2 * i + 1], k1);
            fma2(e10, qr1[2 * i], k0);
            fma2(e11, qr1[2 * i + 1], k1);
        }
        int ki = kk >> 3, kj = kk & 7;
        int bidx = (7 - ki) * 15 + (7 - kj);
        float2 f0 = unpk(add2(e00, e01));
        float2 f1 = unpk(add2(e10, e11));
        float p0 = __expf(f0.x + f0.y + bias_s[bidx + q0i * 15 + q0j]);
        float p1 = __expf(f1.x + f1.y + bias_s[bidx + q1i * 15 + q1j]);
        sum0 += p0; sum1 += p1;
        ull pv0 = dup2(p0), pv1 = dup2(p1);
        const ull* vr = (const ull*)(vs + (kk << 5));
#pragma unroll
        for (int i = 0; i < 16; ++i) {
            ull vv = vr[i];
            fma2(acc0[i], pv0, vv);
            fma2(acc1[i], pv1, vv);
        }
    }

    ull inv0 = dup2(1.0f / sum0), inv1 = dup2(1.0f / sum1);
    ull* op0 = (ull*)(g_att + ((size_t)w * WS2 + q0) * CDIM + h * HD);
    ull* op1 = (ull*)(g_att + ((size_t)w * WS2 + q1) * CDIM + h * HD);
#pragma unroll
    for (int i = 0; i < 16; ++i) {
        op0[i] = mul2(acc0[i], inv0);
        op1[i] = mul2(acc1[i], inv1);
    }
}

// ================= K3: proj GEMM + bias + pixel scatter =================
// grid(2048): 128 g_att rows per CTA; 256 thr; loop 3 N-tiles.
__global__ __launch_bounds__(256) void k_proj(const float* __restrict__ pb,
                                              float* __restrict__ out) {
    extern __shared__ char smem[];
    uint32_t sb = smem_to_u32(smem);
    int tid = threadIdx.x, mt = blockIdx.x;
    int warp = tid >> 5, lane = tid & 31;

    stage_rows_f32(g_att + (size_t)mt * 128 * CDIM, 128, smem + OFF_AH, smem + OFF_AL, tid);

    for (int nt = 0; nt < 3; ++nt) {
        stage_rows_bf16(g_wph + (size_t)nt * 64 * CDIM, g_wpl + (size_t)nt * 64 * CDIM,
                        64, smem + OFF_BH, smem + OFF_BL, tid);
        __syncthreads();

        float acc[8][4];
        mma_core(sb, warp, lane, acc);

#pragma unroll
        for (int half = 0; half < 2; ++half) {
            int p = mt * 128 + warp * 16 + (lane >> 2) + half * 8;
            int w = p >> 6, t = p & 63;
            int b = w >> 10, wh = (w >> 5) & 31, ww = w & 31;
            int ri = t >> 3, ci = t & 7;
            size_t pix = (size_t)((b << 8) + (wh << 3) + ri) * 256 + (ww << 3) + ci;
            float* o = out + pix * CDIM;
#pragma unroll
            for (int nf = 0; nf < 8; ++nf) {
                int oc = nt * 64 + nf * 8 + (lane & 3) * 2;
                float2 bias = *(const float2*)(pb + oc);
                *(float2*)(o + oc) = make_float2(acc[nf][half * 2] + bias.x,
                                                 acc[nf][half * 2 + 1] + bias.y);
            }
        }
        __syncthreads();
    }
}

// ================= launch =================
extern "C" void kernel_launch(void* const* d_in, const int* in_sizes, int n_in,
                              void* d_out, int out_size) {
    const float* x     = (const float*)d_in[0];
    const float* qkvw  = (const float*)d_in[1];
    const float* projw = (const float*)d_in[2];
    const float* pb    = (const float*)d_in[3];
    const float* rpb   = (const float*)d_in[4];
    (void)in_sizes; (void)n_in; (void)out_size;

    cudaFuncSetAttribute(k_qkv,  cudaFuncAttributeMaxDynamicSharedMemorySize, GEMM_SMEM);
    cudaFuncSetAttribute(k_proj, cudaFuncAttributeMaxDynamicSharedMemorySize, GEMM_SMEM);

    k_prep<<<768, 192>>>(qkvw, projw);
    k_qkv <<<2048, 256, GEMM_SMEM>>>(x);
    k_attn<<<dim3(NHD, NW), 32>>>(rpb);
    k_proj<<<2048, 256, GEMM_SMEM>>>(pb, (float*)d_out);
}